// round 2
// baseline (speedup 1.0000x reference)
#include <cuda_runtime.h>
#include <cstdint>
#include <math.h>

#define T_   384
#define B_   48
#define H_   256
#define G3   768
#define NCTA 128
#define RPB  12           // batches per GEMV warp
#define REC_SMEM ((48*256 + 96) * 4)

// ---------------- scratch (device globals; no runtime allocation) ----------------
__device__ float g_gi[(size_t)T_ * B_ * G3];     // bulk input-gates for current layer
__device__ float g_ys0[(size_t)T_ * B_ * H_];    // layer-0 output sequence
__device__ float g_parts[(size_t)T_ * B_ * NCTA];// per-CTA partial skip-gate dots
__device__ float g_skipc[B_];
__device__ float g_dcar[B_];
__device__ unsigned g_count;
__device__ volatile unsigned g_phase;

// ---------------- helpers ----------------
__device__ __forceinline__ float sigm(float x) { return 1.f / (1.f + expf(-x)); }

#define FMA4(acc, wv, hv) { acc = fmaf((wv).x,(hv).x,acc); acc = fmaf((wv).y,(hv).y,acc); \
                            acc = fmaf((wv).z,(hv).z,acc); acc = fmaf((wv).w,(hv).w,acc); }

__device__ __forceinline__ void grid_bar(unsigned target) {
    __syncthreads();
    if (threadIdx.x == 0) {
        __threadfence();
        if (atomicAdd(&g_count, 1u) == NCTA - 1u) {
            atomicExch(&g_count, 0u);
            __threadfence();
            g_phase = target;
        } else {
            while ((int)(g_phase - target) < 0) { }
            __threadfence();
        }
    }
    __syncthreads();
}

// state advance: carry (u,d,s) entering previous step, dn = d_ns of previous step
__device__ __forceinline__ void advance_state(float& u, float& d, float& s, float dn) {
    float bup = rintf(u);
    float nu  = (s > 0.f) ? fminf(fmaxf(u + d, 0.f), 1.f) * (1.f - bup) : dn * bup;
    d = (s > 0.f) ? d : dn;
    s = ((ceilf(0.5f / nu) - 1.f) > 0.f) ? 1.f : 0.f;
    u = nu;
}

__device__ __forceinline__ float part_sum(int t, int b) {
    const float4* p = (const float4*)&g_parts[((size_t)t * B_ + b) * NCTA];
    float4 s4 = make_float4(0.f, 0.f, 0.f, 0.f);
#pragma unroll 8
    for (int c = 0; c < NCTA / 4; c++) {
        float4 v = p[c];
        s4.x += v.x; s4.y += v.y; s4.z += v.z; s4.w += v.w;
    }
    return (s4.x + s4.y) + (s4.z + s4.w);
}

// ---------------- bulk gi GEMM: C[m][n] = sum_k A[m][k] * W[n][k] ----------------
// A: [18432][256] (x or ys0), W: [768][256], C: g_gi [18432][768]. No bias (added in rec).
__global__ void __launch_bounds__(128) gemm_xw(const float* __restrict__ x, int layer,
                                               const float* __restrict__ wih) {
    __shared__ float As[16][64];
    __shared__ float Bs[16][64];
    const float* A = layer ? (const float*)g_ys0 : x;
    const float* W = wih + (size_t)layer * G3 * H_;
    const int tid = threadIdx.x;
    const int m0 = blockIdx.x * 64, n0 = blockIdx.y * 64;
    const int tx = tid & 15, ty = tid >> 4;
    float acc[8][4];
#pragma unroll
    for (int i = 0; i < 8; i++)
#pragma unroll
        for (int j = 0; j < 4; j++) acc[i][j] = 0.f;

    for (int kt = 0; kt < 256; kt += 16) {
#pragma unroll
        for (int i = 0; i < 2; i++) {
            int idx = tid + i * 128;            // 0..255
            int row = idx >> 2, k4 = idx & 3;
            float4 a = *(const float4*)&A[(size_t)(m0 + row) * 256 + kt + k4 * 4];
            As[k4*4+0][row] = a.x; As[k4*4+1][row] = a.y;
            As[k4*4+2][row] = a.z; As[k4*4+3][row] = a.w;
            float4 b = *(const float4*)&W[(size_t)(n0 + row) * 256 + kt + k4 * 4];
            Bs[k4*4+0][row] = b.x; Bs[k4*4+1][row] = b.y;
            Bs[k4*4+2][row] = b.z; Bs[k4*4+3][row] = b.w;
        }
        __syncthreads();
#pragma unroll
        for (int kk = 0; kk < 16; kk++) {
            float4 b4 = *(const float4*)&Bs[kk][tx * 4];
            float4 a0 = *(const float4*)&As[kk][ty * 8];
            float4 a1 = *(const float4*)&As[kk][ty * 8 + 4];
            float am[8] = {a0.x, a0.y, a0.z, a0.w, a1.x, a1.y, a1.z, a1.w};
            float bm[4] = {b4.x, b4.y, b4.z, b4.w};
#pragma unroll
            for (int i = 0; i < 8; i++)
#pragma unroll
                for (int j = 0; j < 4; j++)
                    acc[i][j] = fmaf(am[i], bm[j], acc[i][j]);
        }
        __syncthreads();
    }
#pragma unroll
    for (int i = 0; i < 8; i++) {
        float4 o = make_float4(acc[i][0], acc[i][1], acc[i][2], acc[i][3]);
        *(float4*)&g_gi[(size_t)(m0 + ty * 8 + i) * G3 + n0 + tx * 4] = o;
    }
}

// ---------------- persistent recurrence: one layer ----------------
__global__ void __launch_bounds__(160, 1) rec_kernel(
    int layer,
    const float* __restrict__ hiddens,   // [L][1][H]
    const float* __restrict__ whh,       // [L][768][256]
    const float* __restrict__ bih,       // [L][768]
    const float* __restrict__ bhh,       // [L][768]
    const float* __restrict__ lw,        // [L][1][H]
    const float* __restrict__ lb,        // [L][1]
    float* __restrict__ d_out)           // full output buffer
{
    extern __shared__ float smem[];
    float* h_s  = smem;                  // [48][256]
    float* s_bu = smem + 48 * 256;       // [48]
    float* s_sk = s_bu + 48;             // [48]

    float* ys      = layer ? d_out : g_ys0;                   // [T][B][H] (doubles as h storage)
    float* hs_out  = d_out + (size_t)T_ * B_ * H_ + (size_t)layer * B_ * H_;
    float* tu_out  = d_out + (size_t)T_ * B_ * H_ + 2 * B_ * H_;   // [B][2T]
    const float* gi  = g_gi;
    const float* h0  = hiddens + (size_t)layer * H_;
    const float* wh  = whh + (size_t)layer * G3 * H_;
    const float* bi  = bih + (size_t)layer * G3;
    const float* bh  = bhh + (size_t)layer * G3;
    const float* lwp = lw + (size_t)layer * H_;

    const int cta  = blockIdx.x;
    const int tid  = threadIdx.x;
    const int w    = tid >> 5;
    const int lane = tid & 31;
    const unsigned phase0 = g_phase;

    // ---- per-role persistent registers ----
    // GEMV warps (0-3)
    int jl = lane >> 4, ks = lane & 15;
    int j  = cta * 2 + jl;               // hidden unit index
    int wb = (w < 4 ? w : 0) * RPB;      // warp's first batch
    float4 wr0, wr1, wr2, wr3, wz0, wz1, wz2, wz3, wn0, wn1, wn2, wn3;
    float bir = 0, biz = 0, bin = 0, bhr = 0, bhz = 0, bhn = 0, lwj = 0;
    if (w < 4) {
        const float4* whp = (const float4*)wh;
        int co = ks * 4;
        wr0 = whp[(size_t)(      j) * 64 + co + 0]; wr1 = whp[(size_t)(      j) * 64 + co + 1];
        wr2 = whp[(size_t)(      j) * 64 + co + 2]; wr3 = whp[(size_t)(      j) * 64 + co + 3];
        wz0 = whp[(size_t)(256 + j) * 64 + co + 0]; wz1 = whp[(size_t)(256 + j) * 64 + co + 1];
        wz2 = whp[(size_t)(256 + j) * 64 + co + 2]; wz3 = whp[(size_t)(256 + j) * 64 + co + 3];
        wn0 = whp[(size_t)(512 + j) * 64 + co + 0]; wn1 = whp[(size_t)(512 + j) * 64 + co + 1];
        wn2 = whp[(size_t)(512 + j) * 64 + co + 2]; wn3 = whp[(size_t)(512 + j) * 64 + co + 3];
        bir = bi[j]; biz = bi[j + 256]; bin = bi[j + 512];
        bhr = bh[j]; bhz = bh[j + 256]; bhn = bh[j + 512];
        lwj = lwp[j];
    }
    // state warp (4): lane holds b=lane; lanes<16 also b=lane+32
    float u0 = 1.f, d0 = 0.f, s0 = 0.f, u1 = 1.f, d1 = 0.f, s1 = 0.f, lb_ = 0.f;
    if (w == 4) {
        lb_ = lb[layer];
        if (layer != 0) {
            d0 = g_dcar[lane]; s0 = g_skipc[lane];
            if (lane < 16) { d1 = g_dcar[lane + 32]; s1 = g_skipc[lane + 32]; }
        }
    }

    for (int t = 0; t < T_; t++) {
        float ar[RPB], az[RPB], an[RPB];
        float gir = 0.f, giz = 0.f, gin = 0.f;
        int gbc = wb + (ks < RPB ? ks : RPB - 1);   // clamped batch for uniform control flow

        if (w < 4) {
            // prefetch gi for epilogue (latency hidden under stage+GEMV)
            const float* gp = gi + ((size_t)t * B_ + gbc) * G3 + j;
            gir = gp[0]; giz = gp[256]; gin = gp[512];

            // stage h for this warp's 12 batches
            if (t == 0) {
                const float4* hp = (const float4*)h0;
#pragma unroll
                for (int i = 0; i < 24; i++) {
                    int idx = lane + i * 32;          // 0..767 -> (b_local, k4)
                    ((float4*)&h_s[wb * H_])[idx] = hp[idx & 63];
                }
            } else {
                const float4* src = (const float4*)(ys + ((size_t)(t - 1) * B_ + wb) * H_);
#pragma unroll
                for (int i = 0; i < 24; i++) {
                    int idx = lane + i * 32;
                    ((float4*)&h_s[wb * H_])[idx] = src[idx];
                }
            }
            __syncwarp();

            // GEMV: 3 gates x 12 batches, this lane's 16-wide k-slice
#pragma unroll
            for (int b = 0; b < RPB; b++) {
                const float4* hp4 = (const float4*)&h_s[(wb + b) * H_ + ks * 16];
                float4 h0v = hp4[0], h1v = hp4[1], h2v = hp4[2], h3v = hp4[3];
                float r_ = 0.f, z_ = 0.f, n_ = 0.f;
                FMA4(r_, wr0, h0v); FMA4(r_, wr1, h1v); FMA4(r_, wr2, h2v); FMA4(r_, wr3, h3v);
                FMA4(z_, wz0, h0v); FMA4(z_, wz1, h1v); FMA4(z_, wz2, h2v); FMA4(z_, wz3, h3v);
                FMA4(n_, wn0, h0v); FMA4(n_, wn1, h1v); FMA4(n_, wn2, h2v); FMA4(n_, wn3, h3v);
                ar[b] = r_; az[b] = z_; an[b] = n_;
            }
            // reduce across the 16 k-slices (within each jl half)
#pragma unroll
            for (int b = 0; b < RPB; b++) {
#pragma unroll
                for (int m = 8; m >= 1; m >>= 1) {
                    ar[b] += __shfl_xor_sync(0xffffffffu, ar[b], m);
                    az[b] += __shfl_xor_sync(0xffffffffu, az[b], m);
                    an[b] += __shfl_xor_sync(0xffffffffu, an[b], m);
                }
            }
        } else if (w == 4) {
            // scalar skip-state update using parts[t-1] (deterministic fixed-order sum)
            if (t > 0) {
                float dn0 = sigm(part_sum(t - 1, lane) + lb_);
                advance_state(u0, d0, s0, dn0);
                if (lane < 16) {
                    float dn1 = sigm(part_sum(t - 1, lane + 32) + lb_);
                    advance_state(u1, d1, s1, dn1);
                }
            }
            float bu0 = rintf(u0);
            s_bu[lane] = bu0; s_sk[lane] = s0;
            if (cta == 0) tu_out[(size_t)lane * (2 * T_) + layer * T_ + t] = bu0;
            if (lane < 16) {
                float bu1 = rintf(u1);
                s_bu[lane + 32] = bu1; s_sk[lane + 32] = s1;
                if (cta == 0) tu_out[(size_t)(lane + 32) * (2 * T_) + layer * T_ + t] = bu1;
            }
        }

        __syncthreads();   // s_bu/s_sk + h_s ready

        if (w < 4) {
            // epilogue: this lane handles (batch=gbc, unit=j); all lanes compute, <12 store
            float ghr = 0.f, ghz = 0.f, ghn = 0.f;
#pragma unroll
            for (int b = 0; b < RPB; b++)
                if (ks == b) { ghr = ar[b]; ghz = az[b]; ghn = an[b]; }
            float bu = s_bu[gbc], skf = s_sk[gbc];
            float hprev = h_s[gbc * H_ + j];
            float r = sigm(gir + bir + ghr + bhr);
            float z = sigm(giz + biz + ghz + bhz);
            float n = tanhf(gin + bin + r * (ghn + bhn));
            float cand = (1.f - z) * n + z * hprev;
            float hns = cand * bu;
            float nh = (skf > 0.f) ? hprev * (1.f - bu) : hns;
            float pd = hns * lwj;
            pd += __shfl_xor_sync(0xffffffffu, pd, 16);   // sum the 2 units of this CTA
            if (ks < RPB) {
                ys[((size_t)t * B_ + gbc) * H_ + j] = nh;
                if (t == T_ - 1) hs_out[(size_t)gbc * H_ + j] = nh;
                if (jl == 0) g_parts[((size_t)t * B_ + gbc) * NCTA + cta] = pd;
            }
        }

        grid_bar(phase0 + (unsigned)t + 1u);
    }

    // finalize carry (skip, d) after last step for the next layer
    if (w == 4 && cta == 0) {
        float dn0 = sigm(part_sum(T_ - 1, lane) + lb_);
        advance_state(u0, d0, s0, dn0);
        g_skipc[lane] = s0; g_dcar[lane] = d0;
        if (lane < 16) {
            float dn1 = sigm(part_sum(T_ - 1, lane + 32) + lb_);
            advance_state(u1, d1, s1, dn1);
            g_skipc[lane + 32] = s1; g_dcar[lane + 32] = d1;
        }
    }
}

// ---------------- launcher ----------------
extern "C" void kernel_launch(void* const* d_in, const int* in_sizes, int n_in,
                              void* d_out, int out_size) {
    const float* x   = (const float*)d_in[0];
    const float* hid = (const float*)d_in[1];
    const float* wih = (const float*)d_in[2];
    const float* whh = (const float*)d_in[3];
    const float* bih = (const float*)d_in[4];
    const float* bhh = (const float*)d_in[5];
    const float* lw  = (const float*)d_in[6];
    const float* lb  = (const float*)d_in[7];
    float* out = (float*)d_out;

    cudaFuncSetAttribute(rec_kernel, cudaFuncAttributeMaxDynamicSharedMemorySize, REC_SMEM);

    dim3 ggrid(T_ * B_ / 64, G3 / 64);   // (288, 12)
    gemm_xw<<<ggrid, 128>>>(x, 0, wih);
    rec_kernel<<<NCTA, 160, REC_SMEM>>>(0, hid, whh, bih, bhh, lw, lb, out);
    gemm_xw<<<ggrid, 128>>>(x, 1, wih);
    rec_kernel<<<NCTA, 160, REC_SMEM>>>(1, hid, whh, bih, bhh, lw, lb, out);
}

// round 3
// speedup vs baseline: 1.0096x; 1.0096x over previous
#include <cuda_runtime.h>
#include <cstdint>
#include <math.h>

#define T_   384
#define B_   48
#define H_   256
#define G3   768
#define NCTA 128
#define RPB  12           // batches per GEMV warp
#define HSTR 772          // smem h row stride in words (== 4 mod 32 -> conflict-free LDS)
#define HS_WORDS (15*HSTR + 48*16)      // 12348
#define REC_SMEM ((HS_WORDS + 96) * 4)  // + s_bu/s_sk

// ---------------- scratch (device globals; no runtime allocation) ----------------
__device__ float g_gi[(size_t)T_ * B_ * G3];     // bulk input-gates for current layer
__device__ float g_ys0[(size_t)T_ * B_ * H_];    // layer-0 output sequence
__device__ float g_parts[(size_t)T_ * B_ * NCTA];// per-CTA partial skip-gate dots
__device__ float g_skipc[B_];
__device__ float g_dcar[B_];
__device__ unsigned g_flags[NCTA * 32];          // spread arrive tokens (128B apart)

// ---------------- helpers ----------------
__device__ __forceinline__ float sigm(float x) { return 1.f / (1.f + expf(-x)); }

#define FMA4(acc, wv, hv) { acc = fmaf((wv).x,(hv).x,acc); acc = fmaf((wv).y,(hv).y,acc); \
                            acc = fmaf((wv).z,(hv).z,acc); acc = fmaf((wv).w,(hv).w,acc); }

// state advance: carry (u,d,s) entering previous step, dn = d_ns of previous step
__device__ __forceinline__ void advance_state(float& u, float& d, float& s, float dn) {
    float bup = rintf(u);
    float nu  = (s > 0.f) ? fminf(fmaxf(u + d, 0.f), 1.f) * (1.f - bup) : dn * bup;
    d = (s > 0.f) ? d : dn;
    s = ((ceilf(0.5f / nu) - 1.f) > 0.f) ? 1.f : 0.f;
    u = nu;
}

__device__ __forceinline__ float part_sum(int t, int b) {
    const float4* p = (const float4*)&g_parts[((size_t)t * B_ + b) * NCTA];
    float4 s4 = make_float4(0.f, 0.f, 0.f, 0.f);
#pragma unroll 8
    for (int c = 0; c < NCTA / 4; c++) {
        float4 v = p[c];
        s4.x += v.x; s4.y += v.y; s4.z += v.z; s4.w += v.w;
    }
    return (s4.x + s4.y) + (s4.z + s4.w);
}

// ---------------- bulk gi GEMM: C[m][n] = sum_k A[m][k] * W[n][k] ----------------
__global__ void __launch_bounds__(128) gemm_xw(const float* __restrict__ x, int layer,
                                               const float* __restrict__ wih) {
    __shared__ float As[16][64];
    __shared__ float Bs[16][64];
    const float* A = layer ? (const float*)g_ys0 : x;
    const float* W = wih + (size_t)layer * G3 * H_;
    const int tid = threadIdx.x;
    const int m0 = blockIdx.x * 64, n0 = blockIdx.y * 64;
    const int tx = tid & 15, ty = tid >> 4;
    float acc[8][4];
#pragma unroll
    for (int i = 0; i < 8; i++)
#pragma unroll
        for (int j = 0; j < 4; j++) acc[i][j] = 0.f;

    for (int kt = 0; kt < 256; kt += 16) {
#pragma unroll
        for (int i = 0; i < 2; i++) {
            int idx = tid + i * 128;
            int row = idx >> 2, k4 = idx & 3;
            float4 a = *(const float4*)&A[(size_t)(m0 + row) * 256 + kt + k4 * 4];
            As[k4*4+0][row] = a.x; As[k4*4+1][row] = a.y;
            As[k4*4+2][row] = a.z; As[k4*4+3][row] = a.w;
            float4 b = *(const float4*)&W[(size_t)(n0 + row) * 256 + kt + k4 * 4];
            Bs[k4*4+0][row] = b.x; Bs[k4*4+1][row] = b.y;
            Bs[k4*4+2][row] = b.z; Bs[k4*4+3][row] = b.w;
        }
        __syncthreads();
#pragma unroll
        for (int kk = 0; kk < 16; kk++) {
            float4 b4 = *(const float4*)&Bs[kk][tx * 4];
            float4 a0 = *(const float4*)&As[kk][ty * 8];
            float4 a1 = *(const float4*)&As[kk][ty * 8 + 4];
            float am[8] = {a0.x, a0.y, a0.z, a0.w, a1.x, a1.y, a1.z, a1.w};
            float bm[4] = {b4.x, b4.y, b4.z, b4.w};
#pragma unroll
            for (int i = 0; i < 8; i++)
#pragma unroll
                for (int j = 0; j < 4; j++)
                    acc[i][j] = fmaf(am[i], bm[j], acc[i][j]);
        }
        __syncthreads();
    }
#pragma unroll
    for (int i = 0; i < 8; i++) {
        float4 o = make_float4(acc[i][0], acc[i][1], acc[i][2], acc[i][3]);
        *(float4*)&g_gi[(size_t)(m0 + ty * 8 + i) * G3 + n0 + tx * 4] = o;
    }
}

// ---------------- persistent recurrence: one layer ----------------
__global__ void __launch_bounds__(160, 1) rec_kernel(
    int layer,
    const float* __restrict__ hiddens,   // [L][1][H]
    const float* __restrict__ whh,       // [L][768][256]
    const float* __restrict__ bih,       // [L][768]
    const float* __restrict__ bhh,       // [L][768]
    const float* __restrict__ lw,        // [L][1][H]
    const float* __restrict__ lb,        // [L][1]
    float* __restrict__ d_out)
{
    extern __shared__ float smem[];
    float* h_s  = smem;                      // [16][48][16] padded, stride HSTR
    float* s_bu = smem + HS_WORDS;           // [48]
    float* s_sk = s_bu + 48;                 // [48]

    float* ys      = layer ? d_out : g_ys0;
    float* hs_out  = d_out + (size_t)T_ * B_ * H_ + (size_t)layer * B_ * H_;
    float* tu_out  = d_out + (size_t)T_ * B_ * H_ + 2 * B_ * H_;   // [B][2T]
    const float* gi  = g_gi;
    const float* h0  = hiddens + (size_t)layer * H_;
    const float* wh  = whh + (size_t)layer * G3 * H_;
    const float* bi  = bih + (size_t)layer * G3;
    const float* bh  = bhh + (size_t)layer * G3;
    const float* lwp = lw + (size_t)layer * H_;

    const int cta  = blockIdx.x;
    const int tid  = threadIdx.x;
    const int w    = tid >> 5;
    const int lane = tid & 31;

    // barrier base token (flags are uniform across CTAs at kernel entry)
    const unsigned tok0 = *((volatile unsigned*)&g_flags[cta * 32]);

    // ---- per-role persistent registers ----
    int jl = lane >> 4, ks = lane & 15;
    int j  = cta * 2 + jl;                   // hidden unit index
    int wb = (w < 4 ? w : 0) * RPB;          // warp's first batch
    float4 wr0, wr1, wr2, wr3, wz0, wz1, wz2, wz3, wn0, wn1, wn2, wn3;
    float bir = 0, biz = 0, bin = 0, bhr = 0, bhz = 0, bhn = 0, lwj = 0;
    float gir = 0.f, giz = 0.f, gin = 0.f;
    int gbc = wb + (ks < RPB ? ks : RPB - 1);   // clamped batch (uniform control flow)
    if (w < 4) {
        const float4* whp = (const float4*)wh;
        int co = ks * 4;
        wr0 = whp[(size_t)(      j) * 64 + co + 0]; wr1 = whp[(size_t)(      j) * 64 + co + 1];
        wr2 = whp[(size_t)(      j) * 64 + co + 2]; wr3 = whp[(size_t)(      j) * 64 + co + 3];
        wz0 = whp[(size_t)(256 + j) * 64 + co + 0]; wz1 = whp[(size_t)(256 + j) * 64 + co + 1];
        wz2 = whp[(size_t)(256 + j) * 64 + co + 2]; wz3 = whp[(size_t)(256 + j) * 64 + co + 3];
        wn0 = whp[(size_t)(512 + j) * 64 + co + 0]; wn1 = whp[(size_t)(512 + j) * 64 + co + 1];
        wn2 = whp[(size_t)(512 + j) * 64 + co + 2]; wn3 = whp[(size_t)(512 + j) * 64 + co + 3];
        bir = bi[j]; biz = bi[j + 256]; bin = bi[j + 512];
        bhr = bh[j]; bhz = bh[j + 256]; bhn = bh[j + 512];
        lwj = lwp[j];
        // gi prefetch for t = 0
        const float* gp = gi + (size_t)gbc * G3 + j;
        gir = gp[0]; giz = gp[256]; gin = gp[512];
    }
    // state warp (4): lane holds b=lane; lanes<16 also b=lane+32
    float u0 = 1.f, d0 = 0.f, s0 = 0.f, u1 = 1.f, d1 = 0.f, s1 = 0.f, lb_ = 0.f;
    if (w == 4) {
        lb_ = lb[layer];
        if (layer != 0) {
            d0 = g_dcar[lane]; s0 = g_skipc[lane];
            if (lane < 16) { d1 = g_dcar[lane + 32]; s1 = g_skipc[lane + 32]; }
        }
    }
    // poll addresses: 4 flags per lane
    const volatile unsigned* pf0 = (const volatile unsigned*)&g_flags[(lane * 4 + 0) * 32];
    const volatile unsigned* pf1 = (const volatile unsigned*)&g_flags[(lane * 4 + 1) * 32];
    const volatile unsigned* pf2 = (const volatile unsigned*)&g_flags[(lane * 4 + 2) * 32];
    const volatile unsigned* pf3 = (const volatile unsigned*)&g_flags[(lane * 4 + 3) * 32];

    for (int t = 0; t < T_; t++) {
        float ar[RPB], az[RPB], an[RPB];

        if (w < 4) {
            // ---- stage h for this warp's 12 batches into conflict-free layout ----
            if (t == 0) {
                const float4* hp = (const float4*)h0;
#pragma unroll
                for (int i = 0; i < 24; i++) {
                    int idx = lane + i * 32;
                    int bl = idx >> 6, k4 = idx & 63;
                    float4 v = hp[k4];
                    *(float4*)&h_s[(k4 >> 2) * HSTR + (wb + bl) * 16 + (k4 & 3) * 4] = v;
                }
            } else {
                const float4* src = (const float4*)(ys + ((size_t)(t - 1) * B_ + wb) * H_);
#pragma unroll
                for (int i = 0; i < 24; i++) {
                    int idx = lane + i * 32;
                    int bl = idx >> 6, k4 = idx & 63;
                    float4 v = src[idx];
                    *(float4*)&h_s[(k4 >> 2) * HSTR + (wb + bl) * 16 + (k4 & 3) * 4] = v;
                }
            }
            __syncwarp();

            // ---- GEMV: 3 gates x 12 batches, this lane's 16-wide k-slice ----
#pragma unroll
            for (int b = 0; b < RPB; b++) {
                const float* hb = &h_s[ks * HSTR + (wb + b) * 16];
                float4 h0v = *(const float4*)&hb[0];
                float4 h1v = *(const float4*)&hb[4];
                float4 h2v = *(const float4*)&hb[8];
                float4 h3v = *(const float4*)&hb[12];
                float r_ = 0.f, z_ = 0.f, n_ = 0.f;
                FMA4(r_, wr0, h0v); FMA4(r_, wr1, h1v); FMA4(r_, wr2, h2v); FMA4(r_, wr3, h3v);
                FMA4(z_, wz0, h0v); FMA4(z_, wz1, h1v); FMA4(z_, wz2, h2v); FMA4(z_, wz3, h3v);
                FMA4(n_, wn0, h0v); FMA4(n_, wn1, h1v); FMA4(n_, wn2, h2v); FMA4(n_, wn3, h3v);
                ar[b] = r_; az[b] = z_; an[b] = n_;
            }
#pragma unroll
            for (int b = 0; b < RPB; b++) {
#pragma unroll
                for (int m = 8; m >= 1; m >>= 1) {
                    ar[b] += __shfl_xor_sync(0xffffffffu, ar[b], m);
                    az[b] += __shfl_xor_sync(0xffffffffu, az[b], m);
                    an[b] += __shfl_xor_sync(0xffffffffu, an[b], m);
                }
            }
        } else if (w == 4) {
            // ---- scalar skip-state update using parts[t-1] (deterministic order) ----
            if (t > 0) {
                float dn0 = sigm(part_sum(t - 1, lane) + lb_);
                advance_state(u0, d0, s0, dn0);
                if (lane < 16) {
                    float dn1 = sigm(part_sum(t - 1, lane + 32) + lb_);
                    advance_state(u1, d1, s1, dn1);
                }
            }
            float bu0 = rintf(u0);
            s_bu[lane] = bu0; s_sk[lane] = s0;
            if (cta == 0) tu_out[(size_t)lane * (2 * T_) + layer * T_ + t] = bu0;
            if (lane < 16) {
                float bu1 = rintf(u1);
                s_bu[lane + 32] = bu1; s_sk[lane + 32] = s1;
                if (cta == 0) tu_out[(size_t)(lane + 32) * (2 * T_) + layer * T_ + t] = bu1;
            }
        }

        __syncthreads();   // s_bu/s_sk + h_s ready

        if (w < 4) {
            // ---- epilogue: lane handles (batch=gbc, unit=j) ----
            float ghr = 0.f, ghz = 0.f, ghn = 0.f;
#pragma unroll
            for (int b = 0; b < RPB; b++)
                if (ks == b) { ghr = ar[b]; ghz = az[b]; ghn = an[b]; }
            float bu = s_bu[gbc], skf = s_sk[gbc];
            float hprev = h_s[(j >> 4) * HSTR + gbc * 16 + (j & 15)];
            float r = sigm(gir + bir + ghr + bhr);
            float z = sigm(giz + biz + ghz + bhz);
            float n = tanhf(gin + bin + r * (ghn + bhn));
            float cand = (1.f - z) * n + z * hprev;
            float hns = cand * bu;
            float nh = (skf > 0.f) ? hprev * (1.f - bu) : hns;
            float pd = hns * lwj;
            pd += __shfl_xor_sync(0xffffffffu, pd, 16);
            if (ks < RPB) {
                ys[((size_t)t * B_ + gbc) * H_ + j] = nh;
                if (t == T_ - 1) hs_out[(size_t)gbc * H_ + j] = nh;
                if (jl == 0) g_parts[((size_t)t * B_ + gbc) * NCTA + cta] = pd;
            }
            // prefetch gi for t+1 (hides under the barrier)
            if (t + 1 < T_) {
                const float* gp = gi + ((size_t)(t + 1) * B_ + gbc) * G3 + j;
                gir = gp[0]; giz = gp[256]; gin = gp[512];
            }
            __threadfence();   // publish ys/parts before the CTA's arrive flag
        } else {
            __threadfence();
        }

        __syncthreads();   // all stores in this CTA are fenced

        // ---- atomic-free symmetric grid barrier ----
        unsigned tok = tok0 + (unsigned)t + 1u;
        if (w == 4) {
            if (lane == 0) *((volatile unsigned*)&g_flags[cta * 32]) = tok;
            bool done;
            do {
                unsigned m0 = *pf0, m1 = *pf1, m2 = *pf2, m3 = *pf3;
                int a = min(min((int)(m0 - tok), (int)(m1 - tok)),
                            min((int)(m2 - tok), (int)(m3 - tok)));
                done = __all_sync(0xffffffffu, a >= 0);
            } while (!done);
            __threadfence();
        }
        __syncthreads();   // release the whole CTA into step t+1
    }

    // finalize carry (skip, d) after last step for the next layer
    if (w == 4 && cta == 0) {
        float dn0 = sigm(part_sum(T_ - 1, lane) + lb_);
        advance_state(u0, d0, s0, dn0);
        g_skipc[lane] = s0; g_dcar[lane] = d0;
        if (lane < 16) {
            float dn1 = sigm(part_sum(T_ - 1, lane + 32) + lb_);
            advance_state(u1, d1, s1, dn1);
            g_skipc[lane + 32] = s1; g_dcar[lane + 32] = d1;
        }
    }
}

// ---------------- launcher ----------------
extern "C" void kernel_launch(void* const* d_in, const int* in_sizes, int n_in,
                              void* d_out, int out_size) {
    const float* x   = (const float*)d_in[0];
    const float* hid = (const float*)d_in[1];
    const float* wih = (const float*)d_in[2];
    const float* whh = (const float*)d_in[3];
    const float* bih = (const float*)d_in[4];
    const float* bhh = (const float*)d_in[5];
    const float* lw  = (const float*)d_in[6];
    const float* lb  = (const float*)d_in[7];
    float* out = (float*)d_out;

    cudaFuncSetAttribute(rec_kernel, cudaFuncAttributeMaxDynamicSharedMemorySize, REC_SMEM);

    dim3 ggrid(T_ * B_ / 64, G3 / 64);   // (288, 12)
    gemm_xw<<<ggrid, 128>>>(x, 0, wih);
    rec_kernel<<<NCTA, 160, REC_SMEM>>>(0, hid, whh, bih, bhh, lw, lb, out);
    gemm_xw<<<ggrid, 128>>>(x, 1, wih);
    rec_kernel<<<NCTA, 160, REC_SMEM>>>(1, hid, whh, bih, bhh, lw, lb, out);
}

// round 4
// speedup vs baseline: 1.6810x; 1.6650x over previous
#include <cuda_runtime.h>
#include <cstdint>
#include <math.h>

#define T_   384
#define B_   48
#define H_   256
#define G3   768
#define CSZ  8                 // CTAs per cluster
#define GB   3                 // batches per cluster
#define NCLU (B_/GB)           // 16 clusters
#define NCTA (NCLU*CSZ)        // 128 CTAs
#define THR  256

// ---------------- scratch (device globals; no runtime allocation) ----------------
__device__ float g_gi[(size_t)T_ * B_ * G3];
__device__ float g_ys0[(size_t)T_ * B_ * H_];
__device__ float g_skipc[B_];
__device__ float g_dcar[B_];

// ---------------- helpers ----------------
__device__ __forceinline__ float sigm(float x) { return 1.f / (1.f + expf(-x)); }

#define FMA4(acc, wv, hv) { acc = fmaf((wv).x,(hv).x,acc); acc = fmaf((wv).y,(hv).y,acc); \
                            acc = fmaf((wv).z,(hv).z,acc); acc = fmaf((wv).w,(hv).w,acc); }

__device__ __forceinline__ void advance_state(float& u, float& d, float& s, float dn) {
    float bup = rintf(u);
    float nu  = (s > 0.f) ? fminf(fmaxf(u + d, 0.f), 1.f) * (1.f - bup) : dn * bup;
    d = (s > 0.f) ? d : dn;
    s = ((ceilf(0.5f / nu) - 1.f) > 0.f) ? 1.f : 0.f;
    u = nu;
}

__device__ __forceinline__ unsigned smem_u32(const void* p) {
    unsigned a;
    asm("{ .reg .u64 t; cvta.to.shared.u64 t, %1; cvt.u32.u64 %0, t; }" : "=r"(a) : "l"(p));
    return a;
}
__device__ __forceinline__ unsigned mapa_u32(unsigned a, unsigned r) {
    unsigned o; asm("mapa.shared::cluster.u32 %0, %1, %2;" : "=r"(o) : "r"(a), "r"(r)); return o;
}
__device__ __forceinline__ void st_clu(unsigned a, float v) {
    asm volatile("st.shared::cluster.f32 [%0], %1;" :: "r"(a), "f"(v) : "memory");
}
#define CLUSTER_SYNC() do { asm volatile("barrier.cluster.arrive.aligned;" ::: "memory"); \
                            asm volatile("barrier.cluster.wait.aligned;"   ::: "memory"); } while (0)

// ---------------- bulk gi GEMM: C[m][n] = sum_k A[m][k] * W[n][k] ----------------
__global__ void __launch_bounds__(128) gemm_xw(const float* __restrict__ x, int layer,
                                               const float* __restrict__ wih) {
    __shared__ float As[16][64];
    __shared__ float Bs[16][64];
    const float* A = layer ? (const float*)g_ys0 : x;
    const float* W = wih + (size_t)layer * G3 * H_;
    const int tid = threadIdx.x;
    const int m0 = blockIdx.x * 64, n0 = blockIdx.y * 64;
    const int tx = tid & 15, ty = tid >> 4;
    float acc[8][4];
#pragma unroll
    for (int i = 0; i < 8; i++)
#pragma unroll
        for (int j = 0; j < 4; j++) acc[i][j] = 0.f;

    for (int kt = 0; kt < 256; kt += 16) {
#pragma unroll
        for (int i = 0; i < 2; i++) {
            int idx = tid + i * 128;
            int row = idx >> 2, k4 = idx & 3;
            float4 a = *(const float4*)&A[(size_t)(m0 + row) * 256 + kt + k4 * 4];
            As[k4*4+0][row] = a.x; As[k4*4+1][row] = a.y;
            As[k4*4+2][row] = a.z; As[k4*4+3][row] = a.w;
            float4 b = *(const float4*)&W[(size_t)(n0 + row) * 256 + kt + k4 * 4];
            Bs[k4*4+0][row] = b.x; Bs[k4*4+1][row] = b.y;
            Bs[k4*4+2][row] = b.z; Bs[k4*4+3][row] = b.w;
        }
        __syncthreads();
#pragma unroll
        for (int kk = 0; kk < 16; kk++) {
            float4 b4 = *(const float4*)&Bs[kk][tx * 4];
            float4 a0 = *(const float4*)&As[kk][ty * 8];
            float4 a1 = *(const float4*)&As[kk][ty * 8 + 4];
            float am[8] = {a0.x, a0.y, a0.z, a0.w, a1.x, a1.y, a1.z, a1.w};
            float bm[4] = {b4.x, b4.y, b4.z, b4.w};
#pragma unroll
            for (int i = 0; i < 8; i++)
#pragma unroll
                for (int j = 0; j < 4; j++)
                    acc[i][j] = fmaf(am[i], bm[j], acc[i][j]);
        }
        __syncthreads();
    }
#pragma unroll
    for (int i = 0; i < 8; i++) {
        float4 o = make_float4(acc[i][0], acc[i][1], acc[i][2], acc[i][3]);
        *(float4*)&g_gi[(size_t)(m0 + ty * 8 + i) * G3 + n0 + tx * 4] = o;
    }
}

// ---------------- clustered recurrence: one layer ----------------
// Cluster (8 CTAs) owns 3 batches; CTA rank rk owns units [rk*32, rk*32+32).
// h for the 3 batches lives in each CTA's smem; per step each CTA computes its
// 96 gate-dots x 3 batches (w_hh in registers), updates its 32 units, and
// broadcasts the new h-slice + skip-gate partial to peers via DSMEM.
__global__ void __launch_bounds__(THR, 1) __cluster_dims__(CSZ, 1, 1)
rec_kernel(int layer,
           const float* __restrict__ hiddens,   // [L][1][H]
           const float* __restrict__ whh,       // [L][768][256]
           const float* __restrict__ bih,       // [L][768]
           const float* __restrict__ bhh,       // [L][768]
           const float* __restrict__ lw,        // [L][1][H]
           const float* __restrict__ lb,        // [L][1]
           float* __restrict__ d_out)
{
    __shared__ float h_s[GB][H_];          // full h(t-1) for the cluster's 3 batches
    __shared__ float gh_s[32][3][GB];      // gate dots for this CTA's units
    __shared__ float parts_s[CSZ][GB];     // skip-gate partials from all ranks
    __shared__ float s_bu[GB], s_sk[GB];

    const int tid  = threadIdx.x;
    const int w    = tid >> 5;
    const int lane = tid & 31;
    unsigned rk; asm("mov.u32 %0, %%cluster_ctarank;" : "=r"(rk));
    const int cid = blockIdx.x / CSZ;
    const int bg0 = cid * GB;

    float* ys      = layer ? d_out : g_ys0;
    float* hs_out  = d_out + (size_t)T_ * B_ * H_ + (size_t)layer * B_ * H_;
    float* tu_out  = d_out + (size_t)T_ * B_ * H_ + 2 * B_ * H_;   // [B][2T]
    const float* gi  = g_gi;
    const float* h0  = hiddens + (size_t)layer * H_;
    const float* wh  = whh + (size_t)layer * G3 * H_;
    const float* bi  = bih + (size_t)layer * G3;
    const float* bh  = bhh + (size_t)layer * G3;
    const float* lwp = lw + (size_t)layer * H_;

    // ---- w_hh slices in registers: 6 passes x 16 floats ----
    const int r2 = lane >> 4, k16 = lane & 15;
    float4 wv[6][4];
    const float4* whp = (const float4*)wh;
#pragma unroll
    for (int p = 0; p < 6; p++) {
        int g = p >> 1, usub = (p & 1) * 2 + r2;
        int row = g * 256 + (int)rk * 32 + w * 4 + usub;
#pragma unroll
        for (int i = 0; i < 4; i++) wv[p][i] = whp[(size_t)row * 64 + k16 * 4 + i];
    }
    // epilogue constants (warps 0-2: lane -> (batch=w, unit=lane))
    const int eb = w, eu = lane, egu = (int)rk * 32 + eu;
    float bir = 0, biz = 0, bin = 0, bhr = 0, bhz = 0, bhn = 0, lwj = 0;
    if (w < 3) {
        bir = bi[egu]; biz = bi[256 + egu]; bin = bi[512 + egu];
        bhr = bh[egu]; bhz = bh[256 + egu]; bhn = bh[512 + egu];
        lwj = lwp[egu];
    }
    // skip-state (warp 3, lanes<GB; redundant per CTA, deterministic)
    float su = 1.f, sd = 0.f, ss = 0.f, lb_ = 0.f;
    if (w == 3 && lane < GB) {
        lb_ = lb[layer];
        if (layer) { sd = g_dcar[bg0 + lane]; ss = g_skipc[bg0 + lane]; }
    }
    // DSMEM peer addresses
    unsigned hb = smem_u32(h_s), pb = smem_u32(parts_s);
    unsigned peer_h[CSZ], peer_p[CSZ];
#pragma unroll
    for (int r = 0; r < CSZ; r++) { peer_h[r] = mapa_u32(hb, r); peer_p[r] = mapa_u32(pb, r); }

    // init h_s (each CTA holds the full h for its 3 batches)
    for (int i = tid; i < GB * H_; i += THR) ((float*)h_s)[i] = h0[i & (H_ - 1)];
    __syncthreads();
    CLUSTER_SYNC();

    for (int t = 0; t < T_; t++) {
        // gi prefetch for this step's epilogue
        float gir = 0.f, giz = 0.f, gin = 0.f;
        if (w < 3) {
            const float* gp = gi + ((size_t)t * B_ + bg0 + eb) * G3 + egu;
            gir = gp[0]; giz = gp[256]; gin = gp[512];
        }
        // skip-state update from step t-1 partials
        if (w == 3 && lane < GB) {
            if (t > 0) {
                float ps = 0.f;
#pragma unroll
                for (int r = 0; r < CSZ; r++) ps += parts_s[r][lane];
                advance_state(su, sd, ss, sigm(ps + lb_));
            }
            float bu = rintf(su);
            s_bu[lane] = bu; s_sk[lane] = ss;
            if (rk == 0) tu_out[(size_t)(bg0 + lane) * (2 * T_) + layer * T_ + t] = bu;
        }
        // load this lane's h k-slice once, reuse across all 6 passes
        float4 hreg[GB][4];
#pragma unroll
        for (int b = 0; b < GB; b++)
#pragma unroll
            for (int i = 0; i < 4; i++)
                hreg[b][i] = *(const float4*)&h_s[b][k16 * 16 + i * 4];
        // GEMV: 6 passes, each = 1 gate-row per lane x 3 batches
#pragma unroll
        for (int p = 0; p < 6; p++) {
            float a0 = 0.f, a1 = 0.f, a2 = 0.f;
#pragma unroll
            for (int i = 0; i < 4; i++) {
                FMA4(a0, wv[p][i], hreg[0][i]);
                FMA4(a1, wv[p][i], hreg[1][i]);
                FMA4(a2, wv[p][i], hreg[2][i]);
            }
#pragma unroll
            for (int m = 8; m >= 1; m >>= 1) {
                a0 += __shfl_xor_sync(0xffffffffu, a0, m);
                a1 += __shfl_xor_sync(0xffffffffu, a1, m);
                a2 += __shfl_xor_sync(0xffffffffu, a2, m);
            }
            if (k16 == 0) {
                int u = w * 4 + (p & 1) * 2 + r2, g = p >> 1;
                gh_s[u][g][0] = a0; gh_s[u][g][1] = a1; gh_s[u][g][2] = a2;
            }
        }
        __syncthreads();   // gh_s, s_bu, s_sk ready

        if (w < 3) {
            float ghr = gh_s[eu][0][eb], ghz = gh_s[eu][1][eb], ghn = gh_s[eu][2][eb];
            float bu = s_bu[eb], sk = s_sk[eb];
            float hprev = h_s[eb][egu];
            float r = sigm(gir + bir + ghr + bhr);
            float z = sigm(giz + biz + ghz + bhz);
            float n = tanhf(gin + bin + r * (ghn + bhn));
            float cand = (1.f - z) * n + z * hprev;
            float hns = cand * bu;
            float nh = (sk > 0.f) ? hprev * (1.f - bu) : hns;
            h_s[eb][egu] = nh;
            unsigned off = (unsigned)(eb * H_ + egu) * 4u;
#pragma unroll
            for (int r7 = 0; r7 < CSZ; r7++)
                if (r7 != (int)rk) st_clu(peer_h[r7] + off, nh);
            ys[((size_t)t * B_ + bg0 + eb) * H_ + egu] = nh;
            if (t == T_ - 1) hs_out[(size_t)(bg0 + eb) * H_ + egu] = nh;
            float pd = hns * lwj;
#pragma unroll
            for (int m = 16; m >= 1; m >>= 1) pd += __shfl_xor_sync(0xffffffffu, pd, m);
            if (lane == 0) {
                parts_s[rk][eb] = pd;
                unsigned poff = (unsigned)((int)rk * GB + eb) * 4u;
#pragma unroll
                for (int r7 = 0; r7 < CSZ; r7++)
                    if (r7 != (int)rk) st_clu(peer_p[r7] + poff, pd);
            }
        }
        CLUSTER_SYNC();    // publish h slices + partials cluster-wide
    }

    // layer-0 final carry (skip, d) for layer 1
    if (layer == 0 && w == 3 && lane < GB && rk == 0) {
        float ps = 0.f;
#pragma unroll
        for (int r = 0; r < CSZ; r++) ps += parts_s[r][lane];
        advance_state(su, sd, ss, sigm(ps + lb_));
        g_dcar[bg0 + lane] = sd; g_skipc[bg0 + lane] = ss;
    }
}

// ---------------- launcher ----------------
extern "C" void kernel_launch(void* const* d_in, const int* in_sizes, int n_in,
                              void* d_out, int out_size) {
    const float* x   = (const float*)d_in[0];
    const float* hid = (const float*)d_in[1];
    const float* wih = (const float*)d_in[2];
    const float* whh = (const float*)d_in[3];
    const float* bih = (const float*)d_in[4];
    const float* bhh = (const float*)d_in[5];
    const float* lw  = (const float*)d_in[6];
    const float* lb  = (const float*)d_in[7];
    float* out = (float*)d_out;

    dim3 ggrid(T_ * B_ / 64, G3 / 64);   // (288, 12)
    gemm_xw<<<ggrid, 128>>>(x, 0, wih);
    rec_kernel<<<NCTA, THR>>>(0, hid, whh, bih, bhh, lw, lb, out);
    gemm_xw<<<ggrid, 128>>>(x, 1, wih);
    rec_kernel<<<NCTA, THR>>>(1, hid, whh, bih, bhh, lw, lb, out);
}